// round 9
// baseline (speedup 1.0000x reference)
#include <cuda_runtime.h>
#include <stdint.h>

// Inputs (metadata order):
//   d_in[0] disp        float32 [E,3]   (E = 3,200,000)
//   d_in[1] a           float32 [E]
//   d_in[2] b           float32 [E]
//   d_in[3] edge_index  int32   [2,E]   row0 = src, row1 = dst
//   d_in[4] atom_node   int32   [N]     (N = 100,000)
// Output: float32 [N,3]
//
// force_edge = 2*(b*exp(-r2) - a) * disp ;  out = scatter(+,src) - scatter(+,dst)
//
// Scratch protocol: g_accum is zero at module load (.bss). The gather kernel
// resets each entry to zero after reading it, so every invocation (correctness
// call and each graph replay) starts from an all-zero scratch. No memset node.

#define N_MAX 100352  // >= 100000

__device__ float4 g_accum[N_MAX];  // zero-initialized at module load

__global__ __launch_bounds__(256)
void edge_force_scatter_kernel(const float* __restrict__ disp,
                               const float* __restrict__ a,
                               const float* __restrict__ b,
                               const int* __restrict__ src,
                               const int* __restrict__ dst,
                               int num_edges) {
    int e = blockIdx.x * blockDim.x + threadIdx.x;
    if (e >= num_edges) return;

    float dx = disp[3 * e + 0];
    float dy = disp[3 * e + 1];
    float dz = disp[3 * e + 2];
    float r2 = fmaf(dx, dx, fmaf(dy, dy, dz * dz));

    float ae = a[e];
    float be = b[e];
    float s = 2.0f * fmaf(be, __expf(-r2), -ae);  // 2*(b*exp(-r2) - a)

    float fx = s * dx, fy = s * dy, fz = s * dz;

    int si = src[e];
    int di = dst[e];

    atomicAdd(&g_accum[si], make_float4( fx,  fy,  fz, 0.f));
    atomicAdd(&g_accum[di], make_float4(-fx, -fy, -fz, 0.f));
}

// 1 atom/thread: read float4 accumulator, emit [N,3] output, reset scratch.
__global__ __launch_bounds__(256)
void gather_reset_kernel(float* __restrict__ out, int n) {
    int i = blockIdx.x * blockDim.x + threadIdx.x;
    if (i >= n) return;
    float4 v = g_accum[i];
    g_accum[i] = make_float4(0.f, 0.f, 0.f, 0.f);  // restore zero invariant
    out[3 * i + 0] = v.x;
    out[3 * i + 1] = v.y;
    out[3 * i + 2] = v.z;
}

extern "C" void kernel_launch(void* const* d_in, const int* in_sizes, int n_in,
                              void* d_out, int out_size) {
    const float* disp = (const float*)d_in[0];
    const float* a    = (const float*)d_in[1];
    const float* b    = (const float*)d_in[2];
    const int*   ei   = (const int*)d_in[3];   // int32 [2, E]

    int num_edges = in_sizes[1];               // a is [E]
    const int* src = ei;
    const int* dst = ei + num_edges;

    float* out = (float*)d_out;
    int n_atoms = out_size / 3;

    {
        int threads = 256;
        int blocks = (num_edges + threads - 1) / threads;
        edge_force_scatter_kernel<<<blocks, threads>>>(disp, a, b, src, dst,
                                                       num_edges);
    }
    {
        int threads = 256;
        int blocks = (n_atoms + threads - 1) / threads;
        gather_reset_kernel<<<blocks, threads>>>(out, n_atoms);
    }
}

// round 10
// speedup vs baseline: 1.3025x; 1.3025x over previous
#include <cuda_runtime.h>
#include <stdint.h>

// Inputs (metadata order):
//   d_in[0] disp        float32 [E,3]   (E = 3,200,000)
//   d_in[1] a           float32 [E]
//   d_in[2] b           float32 [E]
//   d_in[3] edge_index  int32   [2,E]   row0 = src, row1 = dst
//   d_in[4] atom_node   int32   [N]     (N = 100,000)
// Output: float32 [N,3]
//
// force_edge = 2*(b*exp(-r2) - a) * disp ;  out = scatter(+,src) - scatter(+,dst)
//
// Pipeline (proven-fast composition):
//   memset node (zeros + L2-warms g_accum) ->
//   1-edge/thread scatter with float4 RED (2 REDs/edge, the algorithmic floor) ->
//   1-atom/thread gather (no reset; memset re-zeros each replay).

#define N_MAX 100352  // >= 100000

__device__ float4 g_accum[N_MAX];

__global__ __launch_bounds__(256)
void edge_force_scatter_kernel(const float* __restrict__ disp,
                               const float* __restrict__ a,
                               const float* __restrict__ b,
                               const int* __restrict__ src,
                               const int* __restrict__ dst,
                               int num_edges) {
    int e = blockIdx.x * blockDim.x + threadIdx.x;
    if (e >= num_edges) return;

    float dx = disp[3 * e + 0];
    float dy = disp[3 * e + 1];
    float dz = disp[3 * e + 2];
    float r2 = fmaf(dx, dx, fmaf(dy, dy, dz * dz));

    float ae = a[e];
    float be = b[e];
    float s = 2.0f * fmaf(be, __expf(-r2), -ae);  // 2*(b*exp(-r2) - a)

    float fx = s * dx, fy = s * dy, fz = s * dz;

    int si = src[e];
    int di = dst[e];

    atomicAdd(&g_accum[si], make_float4( fx,  fy,  fz, 0.f));
    atomicAdd(&g_accum[di], make_float4(-fx, -fy, -fz, 0.f));
}

// 1 atom/thread: read float4 accumulator, write 3 floats. No scratch writes.
__global__ __launch_bounds__(256)
void gather_out_kernel(float* __restrict__ out, int n) {
    int i = blockIdx.x * blockDim.x + threadIdx.x;
    if (i >= n) return;
    float4 v = g_accum[i];
    out[3 * i + 0] = v.x;
    out[3 * i + 1] = v.y;
    out[3 * i + 2] = v.z;
}

extern "C" void kernel_launch(void* const* d_in, const int* in_sizes, int n_in,
                              void* d_out, int out_size) {
    const float* disp = (const float*)d_in[0];
    const float* a    = (const float*)d_in[1];
    const float* b    = (const float*)d_in[2];
    const int*   ei   = (const int*)d_in[3];   // int32 [2, E]

    int num_edges = in_sizes[1];               // a is [E]
    const int* src = ei;
    const int* dst = ei + num_edges;

    float* out = (float*)d_out;
    int n_atoms = out_size / 3;

    // Zero + L2-warm the accumulator (graph-capturable memset node).
    void* accum_ptr = nullptr;
    cudaGetSymbolAddress(&accum_ptr, g_accum);
    cudaMemsetAsync(accum_ptr, 0, (size_t)n_atoms * sizeof(float4));

    {
        int threads = 256;
        int blocks = (num_edges + threads - 1) / threads;
        edge_force_scatter_kernel<<<blocks, threads>>>(disp, a, b, src, dst,
                                                       num_edges);
    }
    {
        int threads = 256;
        int blocks = (n_atoms + threads - 1) / threads;
        gather_out_kernel<<<blocks, threads>>>(out, n_atoms);
    }
}